// round 8
// baseline (speedup 1.0000x reference)
#include <cuda_runtime.h>
#include <math.h>

#define BATCH 4096
#define NPAIR (BATCH / 2)

typedef unsigned long long u64;

// ---- packed fp32x2 helpers (sm_103a; ptxas never emits FFMA2 from C++) ----
__device__ __forceinline__ u64 pack2(float lo, float hi) {
    u64 r; asm("mov.b64 %0, {%1, %2};" : "=l"(r) : "f"(lo), "f"(hi)); return r;
}
__device__ __forceinline__ u64 fma2(u64 a, u64 b, u64 c) {
    u64 d; asm("fma.rn.f32x2 %0, %1, %2, %3;" : "=l"(d) : "l"(a), "l"(b), "l"(c));
    return d;
}
__device__ __forceinline__ void unpack2(u64 v, float& lo, float& hi) {
    asm("mov.b64 {%0, %1}, %2;" : "=f"(lo), "=f"(hi) : "l"(v));
}
__device__ __forceinline__ u64 relu2(u64 v) {
    float lo, hi; unpack2(v, lo, hi);
    return pack2(fmaxf(lo, 0.0f), fmaxf(hi, 0.0f));
}

// Paired-image intermediates
__device__ u64 g_h1_2[(size_t)NPAIR * 10 * 361];   // conv1 out
__device__ u64 g_h2_2[(size_t)NPAIR * 20 * 100];   // conv2 out

// Pre-packed (w,w) weights in global
__device__ u64 g_w1p[1000];
__device__ u64 g_w2p[20000];
__device__ u64 g_w3p[10000];
__device__ u64 g_wfp[7200];

__global__ void pack_weights_kernel(
    const float* __restrict__ w1, const float* __restrict__ w2,
    const float* __restrict__ w3, const float* __restrict__ wf)
{
    const int i = blockIdx.x * 256 + threadIdx.x;
    if (i < 1000)  g_w1p[i] = pack2(w1[i], w1[i]);
    if (i < 20000) g_w2p[i] = pack2(w2[i], w2[i]);
    if (i < 10000) g_w3p[i] = pack2(w3[i], w3[i]);
    if (i < 7200)  g_wfp[i] = pack2(wf[i], wf[i]);
}

// ---------------------------------------------------------------------------
// conv1: [1,28,28] -> relu -> [10,19,19], k10. One block per image PAIR.
// 96 threads, 95 active (R4 config, 78us).
// ---------------------------------------------------------------------------
__global__ __launch_bounds__(96, 8) void conv1_kernel(
    const float* __restrict__ x, const float* __restrict__ b1)
{
    __shared__ u64 s_in2[28 * 29];
    const int bid = blockIdx.x;
    const int tid = threadIdx.x;

    const float* x0 = x + (size_t)(2 * bid) * 784;
    const float* x1 = x0 + 784;
    for (int i = tid; i < 784; i += 96) {
        const int r = i / 28, c = i % 28;
        s_in2[r * 29 + c] = pack2(x0[i], x1[i]);
    }
    __syncthreads();

    if (tid < 95) {
        const int ocg = tid / 19, oy = tid % 19;
        const int oc0 = 2 * ocg;
        const float bv0 = __ldg(&b1[oc0]), bv1 = __ldg(&b1[oc0 + 1]);
        const u64 bi0 = pack2(bv0, bv0), bi1 = pack2(bv1, bv1);
        u64* op0 = &g_h1_2[((size_t)bid * 10 + oc0) * 361 + oy * 19];

        // pass A: outputs q = 0..9
        {
            u64 a0[10], a1[10];
            #pragma unroll
            for (int q = 0; q < 10; q++) { a0[q] = bi0; a1[q] = bi1; }
            for (int ky = 0; ky < 10; ky++) {
                u64 iv[19];
                const u64* rp = &s_in2[(oy + ky) * 29];
                #pragma unroll
                for (int j = 0; j < 19; j++) iv[j] = rp[j];
                const u64* w0p = &g_w1p[oc0 * 100 + ky * 10];
                const u64* w1p = w0p + 100;
                #pragma unroll
                for (int k2 = 0; k2 < 5; k2++) {
                    const ulonglong2 wa = __ldg((const ulonglong2*)(w0p + 2 * k2));
                    const ulonglong2 wb = __ldg((const ulonglong2*)(w1p + 2 * k2));
                    #pragma unroll
                    for (int q = 0; q < 10; q++) {
                        a0[q] = fma2(iv[q + 2 * k2],     wa.x, a0[q]);
                        a0[q] = fma2(iv[q + 2 * k2 + 1], wa.y, a0[q]);
                        a1[q] = fma2(iv[q + 2 * k2],     wb.x, a1[q]);
                        a1[q] = fma2(iv[q + 2 * k2 + 1], wb.y, a1[q]);
                    }
                }
            }
            #pragma unroll
            for (int q = 0; q < 10; q++) {
                op0[q]       = relu2(a0[q]);
                op0[361 + q] = relu2(a1[q]);
            }
        }
        // pass B: outputs q = 10..18
        {
            u64 a0[9], a1[9];
            #pragma unroll
            for (int q = 0; q < 9; q++) { a0[q] = bi0; a1[q] = bi1; }
            for (int ky = 0; ky < 10; ky++) {
                u64 iv[18];
                const u64* rp = &s_in2[(oy + ky) * 29 + 10];
                #pragma unroll
                for (int j = 0; j < 18; j++) iv[j] = rp[j];
                const u64* w0p = &g_w1p[oc0 * 100 + ky * 10];
                const u64* w1p = w0p + 100;
                #pragma unroll
                for (int k2 = 0; k2 < 5; k2++) {
                    const ulonglong2 wa = __ldg((const ulonglong2*)(w0p + 2 * k2));
                    const ulonglong2 wb = __ldg((const ulonglong2*)(w1p + 2 * k2));
                    #pragma unroll
                    for (int q = 0; q < 9; q++) {
                        a0[q] = fma2(iv[q + 2 * k2],     wa.x, a0[q]);
                        a0[q] = fma2(iv[q + 2 * k2 + 1], wa.y, a0[q]);
                        a1[q] = fma2(iv[q + 2 * k2],     wb.x, a1[q]);
                        a1[q] = fma2(iv[q + 2 * k2 + 1], wb.y, a1[q]);
                    }
                }
            }
            #pragma unroll
            for (int q = 0; q < 9; q++) {
                op0[10 + q]  = relu2(a0[q]);
                op0[371 + q] = relu2(a1[q]);
            }
        }
    }
}

// ---------------------------------------------------------------------------
// conv2: [10,19,19] -> relu -> [20,10,10], k10. One block per image PAIR.
// 256 threads, 200 active: thread = (ocg 0..9 [2 oc], oy 0..9, qh 0..1 [5 q]).
// Low regs (~75) -> launch_bounds(256,3) = 24 warps/SM for latency hiding.
// Whole h1 pair in smem (28.9KB), one sync.
// ---------------------------------------------------------------------------
__global__ __launch_bounds__(256, 3) void conv2_kernel(const float* __restrict__ b2)
{
    __shared__ u64 s_h1[3610];      // all 10 input channels, pitch 19
    const int bid = blockIdx.x;
    const int tid = threadIdx.x;
    const u64* h1p = &g_h1_2[(size_t)bid * 3610];

    for (int i = tid; i < 3610; i += 256) s_h1[i] = h1p[i];

    const bool act = tid < 200;
    const int ocg = tid / 20;            // 0..9
    const int oy  = (tid % 20) >> 1;     // 0..9
    const int q0  = (tid & 1) * 5;       // 0 or 5
    const int oc0 = 2 * (ocg < 10 ? ocg : 0);

    u64 a0[5], a1[5];
    {
        const float bv0 = __ldg(&b2[oc0]), bv1 = __ldg(&b2[oc0 + 1]);
        const u64 bi0 = pack2(bv0, bv0), bi1 = pack2(bv1, bv1);
        #pragma unroll
        for (int q = 0; q < 5; q++) { a0[q] = bi0; a1[q] = bi1; }
    }
    __syncthreads();

    if (act) {
        #pragma unroll 1
        for (int c = 0; c < 10; c++) {
            const u64* buf = &s_h1[c * 361];
            for (int ky = 0; ky < 10; ky++) {
                u64 iv[14];
                const u64* rp = &buf[(oy + ky) * 19 + q0];
                #pragma unroll
                for (int j = 0; j < 14; j++) iv[j] = rp[j];
                const u64* w0p = &g_w2p[oc0 * 1000 + c * 100 + ky * 10];
                const u64* w1p = w0p + 1000;
                #pragma unroll
                for (int k2 = 0; k2 < 5; k2++) {
                    const ulonglong2 wa = __ldg((const ulonglong2*)(w0p + 2 * k2));
                    const ulonglong2 wb = __ldg((const ulonglong2*)(w1p + 2 * k2));
                    #pragma unroll
                    for (int q = 0; q < 5; q++) {
                        a0[q] = fma2(iv[q + 2 * k2],     wa.x, a0[q]);
                        a0[q] = fma2(iv[q + 2 * k2 + 1], wa.y, a0[q]);
                        a1[q] = fma2(iv[q + 2 * k2],     wb.x, a1[q]);
                        a1[q] = fma2(iv[q + 2 * k2 + 1], wb.y, a1[q]);
                    }
                }
            }
        }

        u64* op = &g_h2_2[((size_t)bid * 20 + oc0) * 100 + oy * 10 + q0];
        #pragma unroll
        for (int q = 0; q < 5; q++) {
            op[q]       = relu2(a0[q]);
            op[100 + q] = relu2(a1[q]);
        }
    }
}

// ---------------------------------------------------------------------------
// conv3 + FC (R5 config, 111us): one block per 2 image pairs, 128 threads.
// Conv: 120 active, thread = (pp, ocg [2 oc], oy). All channels preloaded.
// ---------------------------------------------------------------------------
__global__ __launch_bounds__(128) void conv3_fc_kernel(
    const float* __restrict__ b3, const float* __restrict__ bf,
    float* __restrict__ out)
{
    __shared__ u64 s_in2[2][2200];   // [pair][c*110 + row*11 + col], pitch 11
    __shared__ u64 s_h2[2][720];     // conv3 relu out per pair
    __shared__ float s_rlo[4][10], s_rhi[4][10];

    const int bid = blockIdx.x;
    const int tid = threadIdx.x;
    const int p0 = 2 * bid;

    for (int i = tid; i < 4000; i += 128) {
        const int pq = i / 2000, rem = i % 2000;
        const int c = rem / 100, j = rem % 100;
        s_in2[pq][c * 110 + (j / 10) * 11 + (j % 10)] =
            g_h2_2[((size_t)(p0 + pq) * 20 + c) * 100 + j];
    }

    const bool act = tid < 120;
    const int pp  = tid / 60;
    const int r   = tid % 60;
    const int ocg = r / 6, oy = r % 6;
    const int oc0 = 2 * ocg;

    u64 a0[6], a1[6];
    if (act) {
        const float bv0 = __ldg(&b3[oc0]), bv1 = __ldg(&b3[oc0 + 1]);
        const u64 bi0 = pack2(bv0, bv0), bi1 = pack2(bv1, bv1);
        #pragma unroll
        for (int q = 0; q < 6; q++) { a0[q] = bi0; a1[q] = bi1; }
    }
    __syncthreads();

    if (act) {
        for (int c = 0; c < 20; c++) {
            const u64* base = &s_in2[pp][c * 110];
            #pragma unroll
            for (int ky = 0; ky < 5; ky++) {
                u64 iv[10];
                const u64* rp = &base[(oy + ky) * 11];
                #pragma unroll
                for (int j = 0; j < 10; j++) iv[j] = rp[j];
                const u64* w0p = &g_w3p[oc0 * 500 + c * 25 + ky * 5];
                const u64* w1p = w0p + 500;
                #pragma unroll
                for (int kx = 0; kx < 5; kx++) {
                    const u64 w0  = __ldg(w0p + kx);
                    const u64 w1v = __ldg(w1p + kx);
                    #pragma unroll
                    for (int q = 0; q < 6; q++) {
                        a0[q] = fma2(iv[q + kx], w0,  a0[q]);
                        a1[q] = fma2(iv[q + kx], w1v, a1[q]);
                    }
                }
            }
        }
    }

    __syncthreads();
    if (act) {
        #pragma unroll
        for (int q = 0; q < 6; q++) {
            s_h2[pp][oc0 * 36 + oy * 6 + q]       = relu2(a0[q]);
            s_h2[pp][(oc0 + 1) * 36 + oy * 6 + q] = relu2(a1[q]);
        }
    }
    __syncthreads();

    // ---- FC: threads 0-63 -> pair p0, 64-127 -> pair p0+1 ----
    {
        const int fpp = tid >> 6;
        const int j0  = tid & 63;
        u64 acc[10];
        #pragma unroll
        for (int o = 0; o < 10; o++) acc[o] = 0ULL;
        for (int j = j0; j < 720; j += 64) {
            const u64 v2 = s_h2[fpp][j];
            #pragma unroll
            for (int o = 0; o < 10; o++)
                acc[o] = fma2(v2, __ldg(&g_wfp[o * 720 + j]), acc[o]);
        }
        const int wid = tid >> 5;
        #pragma unroll
        for (int o = 0; o < 10; o++) {
            float lo, hi; unpack2(acc[o], lo, hi);
            #pragma unroll
            for (int s = 16; s > 0; s >>= 1) {
                lo += __shfl_down_sync(0xffffffffu, lo, s);
                hi += __shfl_down_sync(0xffffffffu, hi, s);
            }
            if ((tid & 31) == 0) { s_rlo[wid][o] = lo; s_rhi[wid][o] = hi; }
        }
    }
    __syncthreads();
    if (tid < 40) {
        const int o  = tid % 10;
        const int im = tid / 10;
        const int fpp  = im >> 1;
        const int half = im & 1;
        const int w0 = 2 * fpp;
        float v;
        if (half == 0) v = s_rlo[w0][o] + s_rlo[w0 + 1][o];
        else           v = s_rhi[w0][o] + s_rhi[w0 + 1][o];
        out[(size_t)(4 * bid + im) * 10 + o] = v + __ldg(&bf[o]);
    }
}

// ---------------------------------------------------------------------------
extern "C" void kernel_launch(void* const* d_in, const int* in_sizes, int n_in,
                              void* d_out, int out_size)
{
    (void)in_sizes; (void)n_in; (void)out_size;
    const float* x  = (const float*)d_in[0];
    const float* w1 = (const float*)d_in[1];
    const float* b1 = (const float*)d_in[2];
    const float* w2 = (const float*)d_in[3];
    const float* b2 = (const float*)d_in[4];
    const float* w3 = (const float*)d_in[5];
    const float* b3 = (const float*)d_in[6];
    const float* wf = (const float*)d_in[7];
    const float* bf = (const float*)d_in[8];
    float* out = (float*)d_out;

    pack_weights_kernel<<<79, 256>>>(w1, w2, w3, wf);
    conv1_kernel<<<NPAIR, 96>>>(x, b1);
    conv2_kernel<<<NPAIR, 256>>>(b2);
    conv3_fc_kernel<<<NPAIR / 2, 128>>>(b3, bf, out);
}

// round 9
// speedup vs baseline: 1.4854x; 1.4854x over previous
#include <cuda_runtime.h>
#include <cuda_bf16.h>
#include <math.h>

#define BATCH 4096
#define NPAIR (BATCH / 2)

typedef unsigned long long u64;
typedef unsigned int u32;

// ---- packed fp32x2 helpers ----
__device__ __forceinline__ u64 pack2(float lo, float hi) {
    u64 r; asm("mov.b64 %0, {%1, %2};" : "=l"(r) : "f"(lo), "f"(hi)); return r;
}
__device__ __forceinline__ u64 fma2(u64 a, u64 b, u64 c) {
    u64 d; asm("fma.rn.f32x2 %0, %1, %2, %3;" : "=l"(d) : "l"(a), "l"(b), "l"(c));
    return d;
}
__device__ __forceinline__ void unpack2(u64 v, float& lo, float& hi) {
    asm("mov.b64 {%0, %1}, %2;" : "=f"(lo), "=f"(hi) : "l"(v));
}
__device__ __forceinline__ u64 relu2(u64 v) {
    float lo, hi; unpack2(v, lo, hi);
    return pack2(fmaxf(lo, 0.0f), fmaxf(hi, 0.0f));
}

// ---- bf16 split helpers ----
__device__ __forceinline__ float bf16r(float x) {
    return __bfloat162float(__float2bfloat16(x));
}
__device__ __forceinline__ u32 bf16pk(float lo, float hi) {
    __nv_bfloat162 t = __floats2bfloat162_rn(lo, hi);
    return reinterpret_cast<u32&>(t);
}

// mma.sync m16n8k16 bf16 (row.col), fp32 accumulate in-place
__device__ __forceinline__ void mma_bf16(float* d, const u32* a, const u32* b) {
    asm volatile(
        "mma.sync.aligned.m16n8k16.row.col.f32.bf16.bf16.f32 "
        "{%0,%1,%2,%3},{%4,%5,%6,%7},{%8,%9},{%0,%1,%2,%3};"
        : "+f"(d[0]), "+f"(d[1]), "+f"(d[2]), "+f"(d[3])
        : "r"(a[0]), "r"(a[1]), "r"(a[2]), "r"(a[3]), "r"(b[0]), "r"(b[1]));
}

// Intermediates
__device__ u64   g_h1_2[(size_t)NPAIR * 10 * 361];   // conv1 out, paired
__device__ float g_h2[(size_t)BATCH * 20 * 100];     // conv2 out, PLANAR fp32

// Pre-packed (w,w) fp32x2 weights (conv1, conv3, fc)
__device__ u64 g_w1p[1000];
__device__ u64 g_w3p[10000];
__device__ u64 g_wfp[7200];

// conv2 B fragments in mma lane layout:
// [ktile(7)][ky(10)][nt(3)][var(2: hi,lo)][reg(2)][lane(32)]
__device__ u32 g_w2frag[7 * 10 * 3 * 2 * 2 * 32];

__global__ void pack_weights_kernel(
    const float* __restrict__ w1, const float* __restrict__ w3,
    const float* __restrict__ wf)
{
    const int i = blockIdx.x * 256 + threadIdx.x;
    if (i < 1000)  g_w1p[i] = pack2(w1[i], w1[i]);
    if (i < 10000) g_w3p[i] = pack2(w3[i], w3[i]);
    if (i < 7200)  g_wfp[i] = pack2(wf[i], wf[i]);
}

__global__ void pack_w2frag_kernel(const float* __restrict__ w2)
{
    int i = blockIdx.x * 256 + threadIdx.x;
    if (i >= 7 * 10 * 3 * 2 * 2 * 32) return;
    int lane = i & 31;  int rest = i >> 5;
    int reg = rest & 1; rest >>= 1;
    int var = rest & 1; rest >>= 1;
    int nt  = rest % 3; rest /= 3;
    int ky  = rest % 10;
    int ktile = rest / 10;

    int t4 = lane & 3, ocol = lane >> 2;
    int oc = nt * 8 + ocol;
    int k0 = ktile * 16 + 2 * t4 + reg * 8;
    float v0 = 0.0f, v1 = 0.0f;
    if (oc < 20) {
        if (k0 < 100) {
            int c = k0 / 10, kx = k0 % 10;
            v0 = w2[oc * 1000 + c * 100 + ky * 10 + kx];
        }
        if (k0 + 1 < 100) {
            int c = (k0 + 1) / 10, kx = (k0 + 1) % 10;
            v1 = w2[oc * 1000 + c * 100 + ky * 10 + kx];
        }
    }
    float h0 = bf16r(v0), h1 = bf16r(v1);
    float o0 = (var == 0) ? h0 : (v0 - h0);
    float o1 = (var == 0) ? h1 : (v1 - h1);
    g_w2frag[i] = bf16pk(o0, o1);
}

// ---------------------------------------------------------------------------
// conv1 (champion config): [1,28,28] -> relu -> [10,19,19], k10.
// One block per image PAIR, 96 threads, f32x2 over the pair.
// ---------------------------------------------------------------------------
__global__ __launch_bounds__(96, 8) void conv1_kernel(
    const float* __restrict__ x, const float* __restrict__ b1)
{
    __shared__ u64 s_in2[28 * 29];
    const int bid = blockIdx.x;
    const int tid = threadIdx.x;

    const float* x0 = x + (size_t)(2 * bid) * 784;
    const float* x1 = x0 + 784;
    for (int i = tid; i < 784; i += 96) {
        const int r = i / 28, c = i % 28;
        s_in2[r * 29 + c] = pack2(x0[i], x1[i]);
    }
    __syncthreads();

    if (tid < 95) {
        const int ocg = tid / 19, oy = tid % 19;
        const int oc0 = 2 * ocg;
        const float bv0 = __ldg(&b1[oc0]), bv1 = __ldg(&b1[oc0 + 1]);
        const u64 bi0 = pack2(bv0, bv0), bi1 = pack2(bv1, bv1);
        u64* op0 = &g_h1_2[((size_t)bid * 10 + oc0) * 361 + oy * 19];

        {
            u64 a0[10], a1[10];
            #pragma unroll
            for (int q = 0; q < 10; q++) { a0[q] = bi0; a1[q] = bi1; }
            for (int ky = 0; ky < 10; ky++) {
                u64 iv[19];
                const u64* rp = &s_in2[(oy + ky) * 29];
                #pragma unroll
                for (int j = 0; j < 19; j++) iv[j] = rp[j];
                const u64* w0p = &g_w1p[oc0 * 100 + ky * 10];
                const u64* w1p = w0p + 100;
                #pragma unroll
                for (int k2 = 0; k2 < 5; k2++) {
                    const ulonglong2 wa = __ldg((const ulonglong2*)(w0p + 2 * k2));
                    const ulonglong2 wb = __ldg((const ulonglong2*)(w1p + 2 * k2));
                    #pragma unroll
                    for (int q = 0; q < 10; q++) {
                        a0[q] = fma2(iv[q + 2 * k2],     wa.x, a0[q]);
                        a0[q] = fma2(iv[q + 2 * k2 + 1], wa.y, a0[q]);
                        a1[q] = fma2(iv[q + 2 * k2],     wb.x, a1[q]);
                        a1[q] = fma2(iv[q + 2 * k2 + 1], wb.y, a1[q]);
                    }
                }
            }
            #pragma unroll
            for (int q = 0; q < 10; q++) {
                op0[q]       = relu2(a0[q]);
                op0[361 + q] = relu2(a1[q]);
            }
        }
        {
            u64 a0[9], a1[9];
            #pragma unroll
            for (int q = 0; q < 9; q++) { a0[q] = bi0; a1[q] = bi1; }
            for (int ky = 0; ky < 10; ky++) {
                u64 iv[18];
                const u64* rp = &s_in2[(oy + ky) * 29 + 10];
                #pragma unroll
                for (int j = 0; j < 18; j++) iv[j] = rp[j];
                const u64* w0p = &g_w1p[oc0 * 100 + ky * 10];
                const u64* w1p = w0p + 100;
                #pragma unroll
                for (int k2 = 0; k2 < 5; k2++) {
                    const ulonglong2 wa = __ldg((const ulonglong2*)(w0p + 2 * k2));
                    const ulonglong2 wb = __ldg((const ulonglong2*)(w1p + 2 * k2));
                    #pragma unroll
                    for (int q = 0; q < 9; q++) {
                        a0[q] = fma2(iv[q + 2 * k2],     wa.x, a0[q]);
                        a0[q] = fma2(iv[q + 2 * k2 + 1], wa.y, a0[q]);
                        a1[q] = fma2(iv[q + 2 * k2],     wb.x, a1[q]);
                        a1[q] = fma2(iv[q + 2 * k2 + 1], wb.y, a1[q]);
                    }
                }
            }
            #pragma unroll
            for (int q = 0; q < 9; q++) {
                op0[10 + q]  = relu2(a0[q]);
                op0[371 + q] = relu2(a1[q]);
            }
        }
    }
}

// ---------------------------------------------------------------------------
// conv2 via tensor-core implicit GEMM (bf16 split, mma.sync m16n8k16).
// One block per image PAIR, 128 threads (4 warps, all active).
// GEMM: M=208 rows (pair positions, pad), N=24 (oc pad), K=100 (c*10+kx)/ky.
// Warp w owns mtiles {w, w+4, w+8, w+12} (valid if <13).
// D = Ahi*Bhi + Alo*Bhi + Ahi*Blo; bias+relu at store; planar g_h2 out.
// ---------------------------------------------------------------------------
__global__ __launch_bounds__(128) void conv2_mma_kernel(const float* __restrict__ b2)
{
    __shared__ u64 s_h1[3610];
    const int bid = blockIdx.x;
    const int tid = threadIdx.x;
    const int wid = tid >> 5, lane = tid & 31;
    const int t4 = lane & 3, gr = lane >> 2;

    const u64* h1p = &g_h1_2[(size_t)bid * 3610];
    for (int i = tid; i < 3610; i += 128) s_h1[i] = h1p[i];
    const float* s_f = reinterpret_cast<const float*>(s_h1);

    float acc[4][3][4];
    #pragma unroll
    for (int mi = 0; mi < 4; mi++)
        #pragma unroll
        for (int nt = 0; nt < 3; nt++)
            #pragma unroll
            for (int r = 0; r < 4; r++) acc[mi][nt][r] = 0.0f;

    // per-(mtile,rowhalf): base offset into the fp32 view of paired h1
    int baseoff[4][2]; bool rv[4][2];
    #pragma unroll
    for (int mi = 0; mi < 4; mi++) {
        const int m = wid + 4 * mi;
        #pragma unroll
        for (int h = 0; h < 2; h++) {
            const int r = m * 16 + gr + 8 * h;
            const bool v = (m < 13) && (r < 200);
            const int img = r / 100, pos = r % 100;
            const int oy = pos / 10, ox = pos % 10;
            rv[mi][h] = v;
            baseoff[mi][h] = v ? ((oy * 19 + ox) * 2 + img) : 0;
        }
    }
    __syncthreads();

    #pragma unroll 1
    for (int ktile = 0; ktile < 7; ktile++) {
        int koff[4]; bool kv[4];
        #pragma unroll
        for (int j = 0; j < 4; j++) {
            const int k = ktile * 16 + 2 * t4 + (j & 1) + (j >> 1) * 8;
            kv[j] = (k < 100);
            const int c = k / 10, kx = k % 10;
            koff[j] = kv[j] ? (c * 722 + kx * 2) : 0;
        }
        #pragma unroll 1
        for (int ky = 0; ky < 10; ky++) {
            // B fragments (pre-swizzled): hi & lo for 3 ntiles
            const u32* bp = &g_w2frag[((ktile * 10 + ky) * 3) * 128 + lane];
            u32 bh[3][2], bl[3][2];
            #pragma unroll
            for (int nt = 0; nt < 3; nt++) {
                bh[nt][0] = __ldg(bp + nt * 128);
                bh[nt][1] = __ldg(bp + nt * 128 + 32);
                bl[nt][0] = __ldg(bp + nt * 128 + 64);
                bl[nt][1] = __ldg(bp + nt * 128 + 96);
            }
            const int kyo = ky * 38;

            #pragma unroll
            for (int mi = 0; mi < 4; mi++) {
                if (wid + 4 * mi < 13) {
                    float vv[2][4];
                    #pragma unroll
                    for (int h = 0; h < 2; h++)
                        #pragma unroll
                        for (int j = 0; j < 4; j++) {
                            const float xval = s_f[baseoff[mi][h] + koff[j] + kyo];
                            vv[h][j] = (rv[mi][h] && kv[j]) ? xval : 0.0f;
                        }
                    u32 ahi[4], alo[4];
                    #pragma unroll
                    for (int h = 0; h < 2; h++)
                        #pragma unroll
                        for (int p = 0; p < 2; p++) {
                            const float x0 = vv[h][2 * p], x1 = vv[h][2 * p + 1];
                            const float h0 = bf16r(x0), h1v = bf16r(x1);
                            ahi[h + 2 * p] = bf16pk(h0, h1v);
                            alo[h + 2 * p] = bf16pk(x0 - h0, x1 - h1v);
                        }
                    #pragma unroll
                    for (int nt = 0; nt < 3; nt++) {
                        mma_bf16(acc[mi][nt], ahi, bh[nt]);
                        mma_bf16(acc[mi][nt], alo, bh[nt]);
                        mma_bf16(acc[mi][nt], ahi, bl[nt]);
                    }
                }
            }
        }
    }

    // store: bias + relu, planar [img][oc][pos]
    #pragma unroll
    for (int mi = 0; mi < 4; mi++) {
        const int m = wid + 4 * mi;
        if (m >= 13) continue;
        #pragma unroll
        for (int h = 0; h < 2; h++) {
            const int r = m * 16 + gr + 8 * h;
            if (r >= 200) continue;
            const int img = r / 100, pos = r % 100;
            float* op = &g_h2[((size_t)(2 * bid + img)) * 2000 + pos];
            #pragma unroll
            for (int nt = 0; nt < 3; nt++) {
                const int oc0 = nt * 8 + 2 * t4;
                if (oc0 < 20) {
                    const float v0 = acc[mi][nt][2 * h] + __ldg(&b2[oc0]);
                    op[oc0 * 100] = fmaxf(v0, 0.0f);
                }
                if (oc0 + 1 < 20) {
                    const float v1 = acc[mi][nt][2 * h + 1] + __ldg(&b2[oc0 + 1]);
                    op[(oc0 + 1) * 100] = fmaxf(v1, 0.0f);
                }
            }
        }
    }
}

// ---------------------------------------------------------------------------
// conv3 + FC (champion config): one block per 2 image pairs, 128 threads.
// Loader packs pairs from planar g_h2.
// ---------------------------------------------------------------------------
__global__ __launch_bounds__(128) void conv3_fc_kernel(
    const float* __restrict__ b3, const float* __restrict__ bf,
    float* __restrict__ out)
{
    __shared__ u64 s_in2[2][2200];   // [pair][c*110 + row*11 + col]
    __shared__ u64 s_h2[2][720];
    __shared__ float s_rlo[4][10], s_rhi[4][10];

    const int bid = blockIdx.x;
    const int tid = threadIdx.x;
    const int p0 = 2 * bid;

    for (int i = tid; i < 4000; i += 128) {
        const int pq = i / 2000, rem = i % 2000;
        const int c = rem / 100, j = rem % 100;
        const int pr = p0 + pq;
        const float lo = g_h2[((size_t)(2 * pr)) * 2000 + c * 100 + j];
        const float hi = g_h2[((size_t)(2 * pr + 1)) * 2000 + c * 100 + j];
        s_in2[pq][c * 110 + (j / 10) * 11 + (j % 10)] = pack2(lo, hi);
    }

    const bool act = tid < 120;
    const int pp  = tid / 60;
    const int r   = tid % 60;
    const int ocg = r / 6, oy = r % 6;
    const int oc0 = 2 * ocg;

    u64 a0[6], a1[6];
    if (act) {
        const float bv0 = __ldg(&b3[oc0]), bv1 = __ldg(&b3[oc0 + 1]);
        const u64 bi0 = pack2(bv0, bv0), bi1 = pack2(bv1, bv1);
        #pragma unroll
        for (int q = 0; q < 6; q++) { a0[q] = bi0; a1[q] = bi1; }
    }
    __syncthreads();

    if (act) {
        for (int c = 0; c < 20; c++) {
            const u64* base = &s_in2[pp][c * 110];
            #pragma unroll
            for (int ky = 0; ky < 5; ky++) {
                u64 iv[10];
                const u64* rp = &base[(oy + ky) * 11];
                #pragma unroll
                for (int j = 0; j < 10; j++) iv[j] = rp[j];
                const u64* w0p = &g_w3p[oc0 * 500 + c * 25 + ky * 5];
                const u64* w1p = w0p + 500;
                #pragma unroll
                for (int kx = 0; kx < 5; kx++) {
                    const u64 w0  = __ldg(w0p + kx);
                    const u64 w1v = __ldg(w1p + kx);
                    #pragma unroll
                    for (int q = 0; q < 6; q++) {
                        a0[q] = fma2(iv[q + kx], w0,  a0[q]);
                        a1[q] = fma2(iv[q + kx], w1v, a1[q]);
                    }
                }
            }
        }
    }

    __syncthreads();
    if (act) {
        #pragma unroll
        for (int q = 0; q < 6; q++) {
            s_h2[pp][oc0 * 36 + oy * 6 + q]       = relu2(a0[q]);
            s_h2[pp][(oc0 + 1) * 36 + oy * 6 + q] = relu2(a1[q]);
        }
    }
    __syncthreads();

    {
        const int fpp = tid >> 6;
        const int j0  = tid & 63;
        u64 acc[10];
        #pragma unroll
        for (int o = 0; o < 10; o++) acc[o] = 0ULL;
        for (int j = j0; j < 720; j += 64) {
            const u64 v2 = s_h2[fpp][j];
            #pragma unroll
            for (int o = 0; o < 10; o++)
                acc[o] = fma2(v2, __ldg(&g_wfp[o * 720 + j]), acc[o]);
        }
        const int wd = tid >> 5;
        #pragma unroll
        for (int o = 0; o < 10; o++) {
            float lo, hi; unpack2(acc[o], lo, hi);
            #pragma unroll
            for (int s = 16; s > 0; s >>= 1) {
                lo += __shfl_down_sync(0xffffffffu, lo, s);
                hi += __shfl_down_sync(0xffffffffu, hi, s);
            }
            if ((tid & 31) == 0) { s_rlo[wd][o] = lo; s_rhi[wd][o] = hi; }
        }
    }
    __syncthreads();
    if (tid < 40) {
        const int o  = tid % 10;
        const int im = tid / 10;
        const int fpp  = im >> 1;
        const int half = im & 1;
        const int w0 = 2 * fpp;
        float v;
        if (half == 0) v = s_rlo[w0][o] + s_rlo[w0 + 1][o];
        else           v = s_rhi[w0][o] + s_rhi[w0 + 1][o];
        out[(size_t)(4 * bid + im) * 10 + o] = v + __ldg(&bf[o]);
    }
}

// ---------------------------------------------------------------------------
extern "C" void kernel_launch(void* const* d_in, const int* in_sizes, int n_in,
                              void* d_out, int out_size)
{
    (void)in_sizes; (void)n_in; (void)out_size;
    const float* x  = (const float*)d_in[0];
    const float* w1 = (const float*)d_in[1];
    const float* b1 = (const float*)d_in[2];
    const float* w2 = (const float*)d_in[3];
    const float* b2 = (const float*)d_in[4];
    const float* w3 = (const float*)d_in[5];
    const float* b3 = (const float*)d_in[6];
    const float* wf = (const float*)d_in[7];
    const float* bf = (const float*)d_in[8];
    float* out = (float*)d_out;

    pack_weights_kernel<<<40, 256>>>(w1, w3, wf);
    pack_w2frag_kernel<<<105, 256>>>(w2);
    conv1_kernel<<<NPAIR, 96>>>(x, b1);
    conv2_mma_kernel<<<NPAIR, 128>>>(b2);
    conv3_fc_kernel<<<NPAIR / 2, 128>>>(b3, bf, out);
}

// round 10
// speedup vs baseline: 1.5639x; 1.0528x over previous
#include <cuda_runtime.h>
#include <cuda_bf16.h>
#include <math.h>

#define BATCH 4096
#define NPAIR (BATCH / 2)

typedef unsigned long long u64;
typedef unsigned int u32;

// ---- packed fp32x2 helpers ----
__device__ __forceinline__ u64 pack2(float lo, float hi) {
    u64 r; asm("mov.b64 %0, {%1, %2};" : "=l"(r) : "f"(lo), "f"(hi)); return r;
}
__device__ __forceinline__ u64 fma2(u64 a, u64 b, u64 c) {
    u64 d; asm("fma.rn.f32x2 %0, %1, %2, %3;" : "=l"(d) : "l"(a), "l"(b), "l"(c));
    return d;
}
__device__ __forceinline__ void unpack2(u64 v, float& lo, float& hi) {
    asm("mov.b64 {%0, %1}, %2;" : "=f"(lo), "=f"(hi) : "l"(v));
}
__device__ __forceinline__ u64 relu2(u64 v) {
    float lo, hi; unpack2(v, lo, hi);
    return pack2(fmaxf(lo, 0.0f), fmaxf(hi, 0.0f));
}

// ---- bf16 split helpers ----
__device__ __forceinline__ float bf16r(float x) {
    return __bfloat162float(__float2bfloat16(x));
}
__device__ __forceinline__ u32 bf16pk(float lo, float hi) {
    __nv_bfloat162 t = __floats2bfloat162_rn(lo, hi);
    return reinterpret_cast<u32&>(t);
}
// split v into (hi bf16 in low16, residual lo bf16 in high16)
__device__ __forceinline__ u32 splitpk(float v) {
    const float h = bf16r(v);
    return bf16pk(h, v - h);
}
__device__ __forceinline__ u32 prmt(u32 a, u32 b, u32 s) {
    u32 d; asm("prmt.b32 %0, %1, %2, %3;" : "=r"(d) : "r"(a), "r"(b), "r"(s));
    return d;
}

// mma.sync m16n8k16 bf16 (row.col), fp32 accumulate in-place
__device__ __forceinline__ void mma_bf16(float* d, const u32* a, const u32* b) {
    asm volatile(
        "mma.sync.aligned.m16n8k16.row.col.f32.bf16.bf16.f32 "
        "{%0,%1,%2,%3},{%4,%5,%6,%7},{%8,%9},{%0,%1,%2,%3};"
        : "+f"(d[0]), "+f"(d[1]), "+f"(d[2]), "+f"(d[3])
        : "r"(a[0]), "r"(a[1]), "r"(a[2]), "r"(a[3]), "r"(b[0]), "r"(b[1]));
}

// Intermediates
__device__ u32   g_h1b[(size_t)BATCH * 3610];        // conv1 out: split-bf16 packed u32, per image [img][c*361+pos]
__device__ float g_h2[(size_t)BATCH * 20 * 100];     // conv2 out, planar fp32

// Pre-packed (w,w) fp32x2 weights (conv1, conv3, fc)
__device__ u64 g_w1p[1000];
__device__ u64 g_w3p[10000];
__device__ u64 g_wfp[7200];

// conv2 B fragments in mma lane layout:
// [ktile(7)][ky(10)][nt(3)][var(2: hi,lo)][reg(2)][lane(32)]
__device__ u32 g_w2frag[7 * 10 * 3 * 2 * 2 * 32];

__global__ void pack_weights_kernel(
    const float* __restrict__ w1, const float* __restrict__ w3,
    const float* __restrict__ wf)
{
    const int i = blockIdx.x * 256 + threadIdx.x;
    if (i < 1000)  g_w1p[i] = pack2(w1[i], w1[i]);
    if (i < 10000) g_w3p[i] = pack2(w3[i], w3[i]);
    if (i < 7200)  g_wfp[i] = pack2(wf[i], wf[i]);
}

__global__ void pack_w2frag_kernel(const float* __restrict__ w2)
{
    int i = blockIdx.x * 256 + threadIdx.x;
    if (i >= 7 * 10 * 3 * 2 * 2 * 32) return;
    int lane = i & 31;  int rest = i >> 5;
    int reg = rest & 1; rest >>= 1;
    int var = rest & 1; rest >>= 1;
    int nt  = rest % 3; rest /= 3;
    int ky  = rest % 10;
    int ktile = rest / 10;

    int t4 = lane & 3, ocol = lane >> 2;
    int oc = nt * 8 + ocol;
    int k0 = ktile * 16 + 2 * t4 + reg * 8;
    float v0 = 0.0f, v1 = 0.0f;
    if (oc < 20) {
        if (k0 < 100) {
            int c = k0 / 10, kx = k0 % 10;
            v0 = w2[oc * 1000 + c * 100 + ky * 10 + kx];
        }
        if (k0 + 1 < 100) {
            int c = (k0 + 1) / 10, kx = (k0 + 1) % 10;
            v1 = w2[oc * 1000 + c * 100 + ky * 10 + kx];
        }
    }
    float h0 = bf16r(v0), h1 = bf16r(v1);
    float o0 = (var == 0) ? h0 : (v0 - h0);
    float o1 = (var == 0) ? h1 : (v1 - h1);
    g_w2frag[i] = bf16pk(o0, o1);
}

// ---------------------------------------------------------------------------
// conv1: [1,28,28] -> relu -> [10,19,19], k10. One block per image PAIR,
// 96 threads, f32x2 over the pair. Epilogue stores split-bf16 u32 per image.
// ---------------------------------------------------------------------------
__global__ __launch_bounds__(96, 8) void conv1_kernel(
    const float* __restrict__ x, const float* __restrict__ b1)
{
    __shared__ u64 s_in2[28 * 29];
    const int bid = blockIdx.x;
    const int tid = threadIdx.x;

    const float* x0 = x + (size_t)(2 * bid) * 784;
    const float* x1 = x0 + 784;
    for (int i = tid; i < 784; i += 96) {
        const int r = i / 28, c = i % 28;
        s_in2[r * 29 + c] = pack2(x0[i], x1[i]);
    }
    __syncthreads();

    if (tid < 95) {
        const int ocg = tid / 19, oy = tid % 19;
        const int oc0 = 2 * ocg;
        const float bv0 = __ldg(&b1[oc0]), bv1 = __ldg(&b1[oc0 + 1]);
        const u64 bi0 = pack2(bv0, bv0), bi1 = pack2(bv1, bv1);
        u32* opA = &g_h1b[(size_t)(2 * bid) * 3610 + oc0 * 361 + oy * 19];
        u32* opB = opA + 3610;   // second image

        {   // pass A: q = 0..9
            u64 a0[10], a1[10];
            #pragma unroll
            for (int q = 0; q < 10; q++) { a0[q] = bi0; a1[q] = bi1; }
            for (int ky = 0; ky < 10; ky++) {
                u64 iv[19];
                const u64* rp = &s_in2[(oy + ky) * 29];
                #pragma unroll
                for (int j = 0; j < 19; j++) iv[j] = rp[j];
                const u64* w0p = &g_w1p[oc0 * 100 + ky * 10];
                const u64* w1p = w0p + 100;
                #pragma unroll
                for (int k2 = 0; k2 < 5; k2++) {
                    const ulonglong2 wa = __ldg((const ulonglong2*)(w0p + 2 * k2));
                    const ulonglong2 wb = __ldg((const ulonglong2*)(w1p + 2 * k2));
                    #pragma unroll
                    for (int q = 0; q < 10; q++) {
                        a0[q] = fma2(iv[q + 2 * k2],     wa.x, a0[q]);
                        a0[q] = fma2(iv[q + 2 * k2 + 1], wa.y, a0[q]);
                        a1[q] = fma2(iv[q + 2 * k2],     wb.x, a1[q]);
                        a1[q] = fma2(iv[q + 2 * k2 + 1], wb.y, a1[q]);
                    }
                }
            }
            #pragma unroll
            for (int q = 0; q < 10; q++) {
                float lo, hi;
                unpack2(a0[q], lo, hi);
                opA[q] = splitpk(fmaxf(lo, 0.0f));
                opB[q] = splitpk(fmaxf(hi, 0.0f));
                unpack2(a1[q], lo, hi);
                opA[361 + q] = splitpk(fmaxf(lo, 0.0f));
                opB[361 + q] = splitpk(fmaxf(hi, 0.0f));
            }
        }
        {   // pass B: q = 10..18
            u64 a0[9], a1[9];
            #pragma unroll
            for (int q = 0; q < 9; q++) { a0[q] = bi0; a1[q] = bi1; }
            for (int ky = 0; ky < 10; ky++) {
                u64 iv[18];
                const u64* rp = &s_in2[(oy + ky) * 29 + 10];
                #pragma unroll
                for (int j = 0; j < 18; j++) iv[j] = rp[j];
                const u64* w0p = &g_w1p[oc0 * 100 + ky * 10];
                const u64* w1p = w0p + 100;
                #pragma unroll
                for (int k2 = 0; k2 < 5; k2++) {
                    const ulonglong2 wa = __ldg((const ulonglong2*)(w0p + 2 * k2));
                    const ulonglong2 wb = __ldg((const ulonglong2*)(w1p + 2 * k2));
                    #pragma unroll
                    for (int q = 0; q < 9; q++) {
                        a0[q] = fma2(iv[q + 2 * k2],     wa.x, a0[q]);
                        a0[q] = fma2(iv[q + 2 * k2 + 1], wa.y, a0[q]);
                        a1[q] = fma2(iv[q + 2 * k2],     wb.x, a1[q]);
                        a1[q] = fma2(iv[q + 2 * k2 + 1], wb.y, a1[q]);
                    }
                }
            }
            #pragma unroll
            for (int q = 0; q < 9; q++) {
                float lo, hi;
                unpack2(a0[q], lo, hi);
                opA[10 + q] = splitpk(fmaxf(lo, 0.0f));
                opB[10 + q] = splitpk(fmaxf(hi, 0.0f));
                unpack2(a1[q], lo, hi);
                opA[371 + q] = splitpk(fmaxf(lo, 0.0f));
                opB[371 + q] = splitpk(fmaxf(hi, 0.0f));
            }
        }
    }
}

// ---------------------------------------------------------------------------
// conv2 tensor-core implicit GEMM. One block per image PAIR, 128 threads.
// A fragments assembled from pre-split bf16 u32 h1 via 2 LDS.32 + 2 PRMT per
// fragment reg (no cvt/sub in the hot loop). No predication: invalid k columns
// have zero B fragments; invalid rows are dropped at store; all fallback
// indices stay in-bounds over finite bf16 data.
// ---------------------------------------------------------------------------
__global__ __launch_bounds__(128) void conv2_mma_kernel(const float* __restrict__ b2)
{
    __shared__ u32 s_h1[7220];       // both images, [img*3610 + c*361 + pos]
    const int bid = blockIdx.x;
    const int tid = threadIdx.x;
    const int wid = tid >> 5, lane = tid & 31;
    const int t4 = lane & 3, gr = lane >> 2;

    const u32* h1p = &g_h1b[(size_t)bid * 7220];
    for (int i = tid; i < 7220; i += 128) s_h1[i] = h1p[i];

    float acc[4][3][4];
    #pragma unroll
    for (int mi = 0; mi < 4; mi++)
        #pragma unroll
        for (int nt = 0; nt < 3; nt++)
            #pragma unroll
            for (int r = 0; r < 4; r++) acc[mi][nt][r] = 0.0f;

    int baseoff[4][2];
    #pragma unroll
    for (int mi = 0; mi < 4; mi++) {
        const int m = wid + 4 * mi;
        #pragma unroll
        for (int h = 0; h < 2; h++) {
            const int r = m * 16 + gr + 8 * h;
            const bool v = (m < 13) && (r < 200);
            const int img = r / 100, pos = r % 100;
            const int oy = pos / 10, ox = pos % 10;
            baseoff[mi][h] = v ? (img * 3610 + oy * 19 + ox) : 0;
        }
    }
    __syncthreads();

    #pragma unroll 1
    for (int ktile = 0; ktile < 7; ktile++) {
        int koff[2];
        #pragma unroll
        for (int p = 0; p < 2; p++) {
            const int k0 = ktile * 16 + 2 * t4 + 8 * p;
            const int c = k0 / 10, kx = k0 % 10;   // k0 even -> kx<=8, pair same c
            koff[p] = (k0 < 100) ? (c * 361 + kx) : 0;
        }
        #pragma unroll 1
        for (int ky = 0; ky < 10; ky++) {
            const u32* bp = &g_w2frag[((ktile * 10 + ky) * 3) * 128 + lane];
            u32 bh[3][2], bl[3][2];
            #pragma unroll
            for (int nt = 0; nt < 3; nt++) {
                bh[nt][0] = __ldg(bp + nt * 128);
                bh[nt][1] = __ldg(bp + nt * 128 + 32);
                bl[nt][0] = __ldg(bp + nt * 128 + 64);
                bl[nt][1] = __ldg(bp + nt * 128 + 96);
            }
            const int kyo = ky * 19;

            #pragma unroll
            for (int mi = 0; mi < 4; mi++) {
                if (wid + 4 * mi < 13) {
                    u32 ahi[4], alo[4];
                    #pragma unroll
                    for (int h = 0; h < 2; h++)
                        #pragma unroll
                        for (int p = 0; p < 2; p++) {
                            const u32* sp = &s_h1[baseoff[mi][h] + koff[p] + kyo];
                            const u32 e0 = sp[0], e1 = sp[1];
                            ahi[h + 2 * p] = prmt(e0, e1, 0x5410u);  // hi halves
                            alo[h + 2 * p] = prmt(e0, e1, 0x7632u);  // lo halves
                        }
                    #pragma unroll
                    for (int nt = 0; nt < 3; nt++) {
                        mma_bf16(acc[mi][nt], ahi, bh[nt]);
                        mma_bf16(acc[mi][nt], alo, bh[nt]);
                        mma_bf16(acc[mi][nt], ahi, bl[nt]);
                    }
                }
            }
        }
    }

    // store: bias + relu, planar [img][oc][pos]
    #pragma unroll
    for (int mi = 0; mi < 4; mi++) {
        const int m = wid + 4 * mi;
        if (m >= 13) continue;
        #pragma unroll
        for (int h = 0; h < 2; h++) {
            const int r = m * 16 + gr + 8 * h;
            if (r >= 200) continue;
            const int img = r / 100, pos = r % 100;
            float* op = &g_h2[((size_t)(2 * bid + img)) * 2000 + pos];
            #pragma unroll
            for (int nt = 0; nt < 3; nt++) {
                const int oc0 = nt * 8 + 2 * t4;
                if (oc0 < 20) {
                    const float v0 = acc[mi][nt][2 * h] + __ldg(&b2[oc0]);
                    op[oc0 * 100] = fmaxf(v0, 0.0f);
                }
                if (oc0 + 1 < 20) {
                    const float v1 = acc[mi][nt][2 * h + 1] + __ldg(&b2[oc0 + 1]);
                    op[(oc0 + 1) * 100] = fmaxf(v1, 0.0f);
                }
            }
        }
    }
}

// ---------------------------------------------------------------------------
// conv3 + FC (champion config): one block per 2 image pairs, 128 threads.
// ---------------------------------------------------------------------------
__global__ __launch_bounds__(128) void conv3_fc_kernel(
    const float* __restrict__ b3, const float* __restrict__ bf,
    float* __restrict__ out)
{
    __shared__ u64 s_in2[2][2200];
    __shared__ u64 s_h2[2][720];
    __shared__ float s_rlo[4][10], s_rhi[4][10];

    const int bid = blockIdx.x;
    const int tid = threadIdx.x;
    const int p0 = 2 * bid;

    for (int i = tid; i < 4000; i += 128) {
        const int pq = i / 2000, rem = i % 2000;
        const int c = rem / 100, j = rem % 100;
        const int pr = p0 + pq;
        const float lo = g_h2[((size_t)(2 * pr)) * 2000 + c * 100 + j];
        const float hi = g_h2[((size_t)(2 * pr + 1)) * 2000 + c * 100 + j];
        s_in2[pq][c * 110 + (j / 10) * 11 + (j % 10)] = pack2(lo, hi);
    }

    const bool act = tid < 120;
    const int pp  = tid / 60;
    const int r   = tid % 60;
    const int ocg = r / 6, oy = r % 6;
    const int oc0 = 2 * ocg;

    u64 a0[6], a1[6];
    if (act) {
        const float bv0 = __ldg(&b3[oc0]), bv1 = __ldg(&b3[oc0 + 1]);
        const u64 bi0 = pack2(bv0, bv0), bi1 = pack2(bv1, bv1);
        #pragma unroll
        for (int q = 0; q < 6; q++) { a0[q] = bi0; a1[q] = bi1; }
    }
    __syncthreads();

    if (act) {
        for (int c = 0; c < 20; c++) {
            const u64* base = &s_in2[pp][c * 110];
            #pragma unroll
            for (int ky = 0; ky < 5; ky++) {
                u64 iv[10];
                const u64* rp = &base[(oy + ky) * 11];
                #pragma unroll
                for (int j = 0; j < 10; j++) iv[j] = rp[j];
                const u64* w0p = &g_w3p[oc0 * 500 + c * 25 + ky * 5];
                const u64* w1p = w0p + 500;
                #pragma unroll
                for (int kx = 0; kx < 5; kx++) {
                    const u64 w0  = __ldg(w0p + kx);
                    const u64 w1v = __ldg(w1p + kx);
                    #pragma unroll
                    for (int q = 0; q < 6; q++) {
                        a0[q] = fma2(iv[q + kx], w0,  a0[q]);
                        a1[q] = fma2(iv[q + kx], w1v, a1[q]);
                    }
                }
            }
        }
    }

    __syncthreads();
    if (act) {
        #pragma unroll
        for (int q = 0; q < 6; q++) {
            s_h2[pp][oc0 * 36 + oy * 6 + q]       = relu2(a0[q]);
            s_h2[pp][(oc0 + 1) * 36 + oy * 6 + q] = relu2(a1[q]);
        }
    }
    __syncthreads();

    {
        const int fpp = tid >> 6;
        const int j0  = tid & 63;
        u64 acc[10];
        #pragma unroll
        for (int o = 0; o < 10; o++) acc[o] = 0ULL;
        for (int j = j0; j < 720; j += 64) {
            const u64 v2 = s_h2[fpp][j];
            #pragma unroll
            for (int o = 0; o < 10; o++)
                acc[o] = fma2(v2, __ldg(&g_wfp[o * 720 + j]), acc[o]);
        }
        const int wd = tid >> 5;
        #pragma unroll
        for (int o = 0; o < 10; o++) {
            float lo, hi; unpack2(acc[o], lo, hi);
            #pragma unroll
            for (int s = 16; s > 0; s >>= 1) {
                lo += __shfl_down_sync(0xffffffffu, lo, s);
                hi += __shfl_down_sync(0xffffffffu, hi, s);
            }
            if ((tid & 31) == 0) { s_rlo[wd][o] = lo; s_rhi[wd][o] = hi; }
        }
    }
    __syncthreads();
    if (tid < 40) {
        const int o  = tid % 10;
        const int im = tid / 10;
        const int fpp  = im >> 1;
        const int half = im & 1;
        const int w0 = 2 * fpp;
        float v;
        if (half == 0) v = s_rlo[w0][o] + s_rlo[w0 + 1][o];
        else           v = s_rhi[w0][o] + s_rhi[w0 + 1][o];
        out[(size_t)(4 * bid + im) * 10 + o] = v + __ldg(&bf[o]);
    }
}

// ---------------------------------------------------------------------------
extern "C" void kernel_launch(void* const* d_in, const int* in_sizes, int n_in,
                              void* d_out, int out_size)
{
    (void)in_sizes; (void)n_in; (void)out_size;
    const float* x  = (const float*)d_in[0];
    const float* w1 = (const float*)d_in[1];
    const float* b1 = (const float*)d_in[2];
    const float* w2 = (const float*)d_in[3];
    const float* b2 = (const float*)d_in[4];
    const float* w3 = (const float*)d_in[5];
    const float* b3 = (const float*)d_in[6];
    const float* wf = (const float*)d_in[7];
    const float* bf = (const float*)d_in[8];
    float* out = (float*)d_out;

    pack_weights_kernel<<<40, 256>>>(w1, w3, wf);
    pack_w2frag_kernel<<<105, 256>>>(w2);
    conv1_kernel<<<NPAIR, 96>>>(x, b1);
    conv2_mma_kernel<<<NPAIR, 128>>>(b2);
    conv3_fc_kernel<<<NPAIR / 2, 128>>>(b3, bf, out);
}

// round 11
// speedup vs baseline: 1.6207x; 1.0364x over previous
#include <cuda_runtime.h>
#include <cuda_bf16.h>
#include <math.h>

#define BATCH 4096
#define NPAIR (BATCH / 2)

typedef unsigned long long u64;
typedef unsigned int u32;

// ---- packed fp32x2 helpers ----
__device__ __forceinline__ u64 pack2(float lo, float hi) {
    u64 r; asm("mov.b64 %0, {%1, %2};" : "=l"(r) : "f"(lo), "f"(hi)); return r;
}
__device__ __forceinline__ u64 fma2(u64 a, u64 b, u64 c) {
    u64 d; asm("fma.rn.f32x2 %0, %1, %2, %3;" : "=l"(d) : "l"(a), "l"(b), "l"(c));
    return d;
}
__device__ __forceinline__ void unpack2(u64 v, float& lo, float& hi) {
    asm("mov.b64 {%0, %1}, %2;" : "=f"(lo), "=f"(hi) : "l"(v));
}
__device__ __forceinline__ u64 relu2(u64 v) {
    float lo, hi; unpack2(v, lo, hi);
    return pack2(fmaxf(lo, 0.0f), fmaxf(hi, 0.0f));
}

// ---- bf16 split helpers ----
__device__ __forceinline__ float bf16r(float x) {
    return __bfloat162float(__float2bfloat16(x));
}
__device__ __forceinline__ u32 bf16pk(float lo, float hi) {
    __nv_bfloat162 t = __floats2bfloat162_rn(lo, hi);
    return reinterpret_cast<u32&>(t);
}
__device__ __forceinline__ u32 splitpk(float v) {
    const float h = bf16r(v);
    return bf16pk(h, v - h);
}
__device__ __forceinline__ u32 prmt(u32 a, u32 b, u32 s) {
    u32 d; asm("prmt.b32 %0, %1, %2, %3;" : "=r"(d) : "r"(a), "r"(b), "r"(s));
    return d;
}

// mma.sync m16n8k16 bf16 (row.col), fp32 accumulate in-place
__device__ __forceinline__ void mma_bf16(float* d, const u32* a, const u32* b) {
    asm volatile(
        "mma.sync.aligned.m16n8k16.row.col.f32.bf16.bf16.f32 "
        "{%0,%1,%2,%3},{%4,%5,%6,%7},{%8,%9},{%0,%1,%2,%3};"
        : "+f"(d[0]), "+f"(d[1]), "+f"(d[2]), "+f"(d[3])
        : "r"(a[0]), "r"(a[1]), "r"(a[2]), "r"(a[3]), "r"(b[0]), "r"(b[1]));
}

// Intermediates
__device__ u32   g_h1b[(size_t)BATCH * 3610];        // conv1 out: split-bf16 u32
__device__ float g_h2[(size_t)BATCH * 20 * 100];     // conv2 out, planar fp32

// Pre-packed (w,w) fp32x2 weights (conv1, conv3, fc)
__device__ u64 g_w1p[1000];
__device__ u64 g_w3p[10000];
__device__ u64 g_wfp[7200];

// conv2 B fragments, linearized K:
// [kt(63)][nt(3)][var(2: hi,lo)][reg(2)][lane(32)]
__device__ u32 g_w2frag[63 * 3 * 2 * 2 * 32];

__global__ void pack_weights_kernel(
    const float* __restrict__ w1, const float* __restrict__ w3,
    const float* __restrict__ wf)
{
    const int i = blockIdx.x * 256 + threadIdx.x;
    if (i < 1000)  g_w1p[i] = pack2(w1[i], w1[i]);
    if (i < 10000) g_w3p[i] = pack2(w3[i], w3[i]);
    if (i < 7200)  g_wfp[i] = pack2(wf[i], wf[i]);
}

__global__ void pack_w2frag_kernel(const float* __restrict__ w2)
{
    int i = blockIdx.x * 256 + threadIdx.x;
    if (i >= 63 * 3 * 2 * 2 * 32) return;
    int lane = i & 31;  int rest = i >> 5;
    int reg = rest & 1; rest >>= 1;
    int var = rest & 1; rest >>= 1;
    int nt  = rest % 3;
    int kt  = rest / 3;

    int t4 = lane & 3, ocol = lane >> 2;
    int oc = nt * 8 + ocol;
    int k0 = kt * 16 + 2 * t4 + reg * 8;   // linear k = c*100 + ky*10 + kx
    float v0 = 0.0f, v1 = 0.0f;
    if (oc < 20) {
        if (k0 < 1000)     v0 = w2[oc * 1000 + k0];
        if (k0 + 1 < 1000) v1 = w2[oc * 1000 + k0 + 1];
    }
    float h0 = bf16r(v0), h1 = bf16r(v1);
    float o0 = (var == 0) ? h0 : (v0 - h0);
    float o1 = (var == 0) ? h1 : (v1 - h1);
    g_w2frag[i] = bf16pk(o0, o1);
}

// ---------------------------------------------------------------------------
// conv1: [1,28,28] -> relu -> [10,19,19], k10. One block per image PAIR,
// 96 threads, f32x2 over the pair. Epilogue stores split-bf16 u32 per image.
// ---------------------------------------------------------------------------
__global__ __launch_bounds__(96, 8) void conv1_kernel(
    const float* __restrict__ x, const float* __restrict__ b1)
{
    __shared__ u64 s_in2[28 * 29];
    const int bid = blockIdx.x;
    const int tid = threadIdx.x;

    const float* x0 = x + (size_t)(2 * bid) * 784;
    const float* x1 = x0 + 784;
    for (int i = tid; i < 784; i += 96) {
        const int r = i / 28, c = i % 28;
        s_in2[r * 29 + c] = pack2(x0[i], x1[i]);
    }
    __syncthreads();

    if (tid < 95) {
        const int ocg = tid / 19, oy = tid % 19;
        const int oc0 = 2 * ocg;
        const float bv0 = __ldg(&b1[oc0]), bv1 = __ldg(&b1[oc0 + 1]);
        const u64 bi0 = pack2(bv0, bv0), bi1 = pack2(bv1, bv1);
        u32* opA = &g_h1b[(size_t)(2 * bid) * 3610 + oc0 * 361 + oy * 19];
        u32* opB = opA + 3610;

        {   // pass A: q = 0..9
            u64 a0[10], a1[10];
            #pragma unroll
            for (int q = 0; q < 10; q++) { a0[q] = bi0; a1[q] = bi1; }
            for (int ky = 0; ky < 10; ky++) {
                u64 iv[19];
                const u64* rp = &s_in2[(oy + ky) * 29];
                #pragma unroll
                for (int j = 0; j < 19; j++) iv[j] = rp[j];
                const u64* w0p = &g_w1p[oc0 * 100 + ky * 10];
                const u64* w1p = w0p + 100;
                #pragma unroll
                for (int k2 = 0; k2 < 5; k2++) {
                    const ulonglong2 wa = __ldg((const ulonglong2*)(w0p + 2 * k2));
                    const ulonglong2 wb = __ldg((const ulonglong2*)(w1p + 2 * k2));
                    #pragma unroll
                    for (int q = 0; q < 10; q++) {
                        a0[q] = fma2(iv[q + 2 * k2],     wa.x, a0[q]);
                        a0[q] = fma2(iv[q + 2 * k2 + 1], wa.y, a0[q]);
                        a1[q] = fma2(iv[q + 2 * k2],     wb.x, a1[q]);
                        a1[q] = fma2(iv[q + 2 * k2 + 1], wb.y, a1[q]);
                    }
                }
            }
            #pragma unroll
            for (int q = 0; q < 10; q++) {
                float lo, hi;
                unpack2(a0[q], lo, hi);
                opA[q] = splitpk(fmaxf(lo, 0.0f));
                opB[q] = splitpk(fmaxf(hi, 0.0f));
                unpack2(a1[q], lo, hi);
                opA[361 + q] = splitpk(fmaxf(lo, 0.0f));
                opB[361 + q] = splitpk(fmaxf(hi, 0.0f));
            }
        }
        {   // pass B: q = 10..18
            u64 a0[9], a1[9];
            #pragma unroll
            for (int q = 0; q < 9; q++) { a0[q] = bi0; a1[q] = bi1; }
            for (int ky = 0; ky < 10; ky++) {
                u64 iv[18];
                const u64* rp = &s_in2[(oy + ky) * 29 + 10];
                #pragma unroll
                for (int j = 0; j < 18; j++) iv[j] = rp[j];
                const u64* w0p = &g_w1p[oc0 * 100 + ky * 10];
                const u64* w1p = w0p + 100;
                #pragma unroll
                for (int k2 = 0; k2 < 5; k2++) {
                    const ulonglong2 wa = __ldg((const ulonglong2*)(w0p + 2 * k2));
                    const ulonglong2 wb = __ldg((const ulonglong2*)(w1p + 2 * k2));
                    #pragma unroll
                    for (int q = 0; q < 9; q++) {
                        a0[q] = fma2(iv[q + 2 * k2],     wa.x, a0[q]);
                        a0[q] = fma2(iv[q + 2 * k2 + 1], wa.y, a0[q]);
                        a1[q] = fma2(iv[q + 2 * k2],     wb.x, a1[q]);
                        a1[q] = fma2(iv[q + 2 * k2 + 1], wb.y, a1[q]);
                    }
                }
            }
            #pragma unroll
            for (int q = 0; q < 9; q++) {
                float lo, hi;
                unpack2(a0[q], lo, hi);
                opA[10 + q] = splitpk(fmaxf(lo, 0.0f));
                opB[10 + q] = splitpk(fmaxf(hi, 0.0f));
                unpack2(a1[q], lo, hi);
                opA[371 + q] = splitpk(fmaxf(lo, 0.0f));
                opB[371 + q] = splitpk(fmaxf(hi, 0.0f));
            }
        }
    }
}

// ---------------------------------------------------------------------------
// conv2 tensor-core implicit GEMM, linearized K (63 epochs) with register
// double-buffered B fragments (LDG latency hidden behind MMAs).
// One block per image PAIR, 128 threads.
// ---------------------------------------------------------------------------
__global__ __launch_bounds__(128) void conv2_mma_kernel(const float* __restrict__ b2)
{
    __shared__ u32 s_h1[7220];       // both images, [img*3610 + c*361 + pos]
    const int bid = blockIdx.x;
    const int tid = threadIdx.x;
    const int wid = tid >> 5, lane = tid & 31;
    const int t4 = lane & 3, gr = lane >> 2;

    const u32* h1p = &g_h1b[(size_t)bid * 7220];
    for (int i = tid; i < 7220; i += 128) s_h1[i] = h1p[i];

    float acc[4][3][4];
    #pragma unroll
    for (int mi = 0; mi < 4; mi++)
        #pragma unroll
        for (int nt = 0; nt < 3; nt++)
            #pragma unroll
            for (int r = 0; r < 4; r++) acc[mi][nt][r] = 0.0f;

    int baseoff[4][2];
    #pragma unroll
    for (int mi = 0; mi < 4; mi++) {
        const int m = wid + 4 * mi;
        #pragma unroll
        for (int h = 0; h < 2; h++) {
            const int r = m * 16 + gr + 8 * h;
            const bool v = (m < 13) && (r < 200);
            const int img = r / 100, pos = r % 100;
            const int oy = pos / 10, ox = pos % 10;
            baseoff[mi][h] = v ? (img * 3610 + oy * 19 + ox) : 0;
        }
    }
    __syncthreads();

    // B double buffer: bc[j], j = nt*4 + var*2 + reg
    u32 bc[12];
    {
        const u32* bp = &g_w2frag[lane];
        #pragma unroll
        for (int j = 0; j < 12; j++) bc[j] = __ldg(bp + j * 32);
    }

    #pragma unroll 1
    for (int kt = 0; kt < 63; kt++) {
        // prefetch next epoch's B while this epoch's MMAs run
        u32 bn[12];
        const int ktn = (kt < 62) ? (kt + 1) : 62;
        {
            const u32* bp = &g_w2frag[ktn * 384 + lane];
            #pragma unroll
            for (int j = 0; j < 12; j++) bn[j] = __ldg(bp + j * 32);
        }

        int koff[2];
        #pragma unroll
        for (int p = 0; p < 2; p++) {
            const int k0 = kt * 16 + 2 * t4 + 8 * p;
            const int c = k0 / 100, rem = k0 % 100;
            const int ky = rem / 10, kx = rem % 10;
            koff[p] = (k0 < 1000) ? (c * 361 + ky * 19 + kx) : 0;
        }

        #pragma unroll
        for (int mi = 0; mi < 4; mi++) {
            if (wid + 4 * mi < 13) {
                u32 ahi[4], alo[4];
                #pragma unroll
                for (int h = 0; h < 2; h++)
                    #pragma unroll
                    for (int p = 0; p < 2; p++) {
                        const u32* sp = &s_h1[baseoff[mi][h] + koff[p]];
                        const u32 e0 = sp[0], e1 = sp[1];
                        ahi[h + 2 * p] = prmt(e0, e1, 0x5410u);
                        alo[h + 2 * p] = prmt(e0, e1, 0x7632u);
                    }
                #pragma unroll
                for (int nt = 0; nt < 3; nt++) {
                    mma_bf16(acc[mi][nt], ahi, &bc[nt * 4]);      // ahi*bh
                    mma_bf16(acc[mi][nt], alo, &bc[nt * 4]);      // alo*bh
                    mma_bf16(acc[mi][nt], ahi, &bc[nt * 4 + 2]);  // ahi*bl
                }
            }
        }

        #pragma unroll
        for (int j = 0; j < 12; j++) bc[j] = bn[j];
    }

    // store: bias + relu, planar [img][oc][pos]
    #pragma unroll
    for (int mi = 0; mi < 4; mi++) {
        const int m = wid + 4 * mi;
        if (m >= 13) continue;
        #pragma unroll
        for (int h = 0; h < 2; h++) {
            const int r = m * 16 + gr + 8 * h;
            if (r >= 200) continue;
            const int img = r / 100, pos = r % 100;
            float* op = &g_h2[((size_t)(2 * bid + img)) * 2000 + pos];
            #pragma unroll
            for (int nt = 0; nt < 3; nt++) {
                const int oc0 = nt * 8 + 2 * t4;
                if (oc0 < 20) {
                    const float v0 = acc[mi][nt][2 * h] + __ldg(&b2[oc0]);
                    op[oc0 * 100] = fmaxf(v0, 0.0f);
                }
                if (oc0 + 1 < 20) {
                    const float v1 = acc[mi][nt][2 * h + 1] + __ldg(&b2[oc0 + 1]);
                    op[(oc0 + 1) * 100] = fmaxf(v1, 0.0f);
                }
            }
        }
    }
}

// ---------------------------------------------------------------------------
// conv3 + FC (champion config): one block per 2 image pairs, 128 threads.
// ---------------------------------------------------------------------------
__global__ __launch_bounds__(128) void conv3_fc_kernel(
    const float* __restrict__ b3, const float* __restrict__ bf,
    float* __restrict__ out)
{
    __shared__ u64 s_in2[2][2200];
    __shared__ u64 s_h2[2][720];
    __shared__ float s_rlo[4][10], s_rhi[4][10];

    const int bid = blockIdx.x;
    const int tid = threadIdx.x;
    const int p0 = 2 * bid;

    for (int i = tid; i < 4000; i += 128) {
        const int pq = i / 2000, rem = i % 2000;
        const int c = rem / 100, j = rem % 100;
        const int pr = p0 + pq;
        const float lo = g_h2[((size_t)(2 * pr)) * 2000 + c * 100 + j];
        const float hi = g_h2[((size_t)(2 * pr + 1)) * 2000 + c * 100 + j];
        s_in2[pq][c * 110 + (j / 10) * 11 + (j % 10)] = pack2(lo, hi);
    }

    const bool act = tid < 120;
    const int pp  = tid / 60;
    const int r   = tid % 60;
    const int ocg = r / 6, oy = r % 6;
    const int oc0 = 2 * ocg;

    u64 a0[6], a1[6];
    if (act) {
        const float bv0 = __ldg(&b3[oc0]), bv1 = __ldg(&b3[oc0 + 1]);
        const u64 bi0 = pack2(bv0, bv0), bi1 = pack2(bv1, bv1);
        #pragma unroll
        for (int q = 0; q < 6; q++) { a0[q] = bi0; a1[q] = bi1; }
    }
    __syncthreads();

    if (act) {
        for (int c = 0; c < 20; c++) {
            const u64* base = &s_in2[pp][c * 110];
            #pragma unroll
            for (int ky = 0; ky < 5; ky++) {
                u64 iv[10];
                const u64* rp = &base[(oy + ky) * 11];
                #pragma unroll
                for (int j = 0; j < 10; j++) iv[j] = rp[j];
                const u64* w0p = &g_w3p[oc0 * 500 + c * 25 + ky * 5];
                const u64* w1p = w0p + 500;
                #pragma unroll
                for (int kx = 0; kx < 5; kx++) {
                    const u64 w0  = __ldg(w0p + kx);
                    const u64 w1v = __ldg(w1p + kx);
                    #pragma unroll
                    for (int q = 0; q < 6; q++) {
                        a0[q] = fma2(iv[q + kx], w0,  a0[q]);
                        a1[q] = fma2(iv[q + kx], w1v, a1[q]);
                    }
                }
            }
        }
    }

    __syncthreads();
    if (act) {
        #pragma unroll
        for (int q = 0; q < 6; q++) {
            s_h2[pp][oc0 * 36 + oy * 6 + q]       = relu2(a0[q]);
            s_h2[pp][(oc0 + 1) * 36 + oy * 6 + q] = relu2(a1[q]);
        }
    }
    __syncthreads();

    {
        const int fpp = tid >> 6;
        const int j0  = tid & 63;
        u64 acc[10];
        #pragma unroll
        for (int o = 0; o < 10; o++) acc[o] = 0ULL;
        for (int j = j0; j < 720; j += 64) {
            const u64 v2 = s_h2[fpp][j];
            #pragma unroll
            for (int o = 0; o < 10; o++)
                acc[o] = fma2(v2, __ldg(&g_wfp[o * 720 + j]), acc[o]);
        }
        const int wd = tid >> 5;
        #pragma unroll
        for (int o = 0; o < 10; o++) {
            float lo, hi; unpack2(acc[o], lo, hi);
            #pragma unroll
            for (int s = 16; s > 0; s >>= 1) {
                lo += __shfl_down_sync(0xffffffffu, lo, s);
                hi += __shfl_down_sync(0xffffffffu, hi, s);
            }
            if ((tid & 31) == 0) { s_rlo[wd][o] = lo; s_rhi[wd][o] = hi; }
        }
    }
    __syncthreads();
    if (tid < 40) {
        const int o  = tid % 10;
        const int im = tid / 10;
        const int fpp  = im >> 1;
        const int half = im & 1;
        const int w0 = 2 * fpp;
        float v;
        if (half == 0) v = s_rlo[w0][o] + s_rlo[w0 + 1][o];
        else           v = s_rhi[w0][o] + s_rhi[w0 + 1][o];
        out[(size_t)(4 * bid + im) * 10 + o] = v + __ldg(&bf[o]);
    }
}

// ---------------------------------------------------------------------------
extern "C" void kernel_launch(void* const* d_in, const int* in_sizes, int n_in,
                              void* d_out, int out_size)
{
    (void)in_sizes; (void)n_in; (void)out_size;
    const float* x  = (const float*)d_in[0];
    const float* w1 = (const float*)d_in[1];
    const float* b1 = (const float*)d_in[2];
    const float* w2 = (const float*)d_in[3];
    const float* b2 = (const float*)d_in[4];
    const float* w3 = (const float*)d_in[5];
    const float* b3 = (const float*)d_in[6];
    const float* wf = (const float*)d_in[7];
    const float* bf = (const float*)d_in[8];
    float* out = (float*)d_out;

    pack_weights_kernel<<<40, 256>>>(w1, w3, wf);
    pack_w2frag_kernel<<<95, 256>>>(w2);
    conv1_kernel<<<NPAIR, 96>>>(x, b1);
    conv2_mma_kernel<<<NPAIR, 128>>>(b2);
    conv3_fc_kernel<<<NPAIR / 2, 128>>>(b3, bf, out);
}

// round 12
// speedup vs baseline: 1.6577x; 1.0228x over previous
#include <cuda_runtime.h>
#include <cuda_bf16.h>
#include <math.h>

#define BATCH 4096
#define NPAIR (BATCH / 2)

typedef unsigned long long u64;
typedef unsigned int u32;
typedef unsigned short u16;

// ---- packed fp32x2 helpers ----
__device__ __forceinline__ u64 pack2(float lo, float hi) {
    u64 r; asm("mov.b64 %0, {%1, %2};" : "=l"(r) : "f"(lo), "f"(hi)); return r;
}
__device__ __forceinline__ u64 fma2(u64 a, u64 b, u64 c) {
    u64 d; asm("fma.rn.f32x2 %0, %1, %2, %3;" : "=l"(d) : "l"(a), "l"(b), "l"(c));
    return d;
}
__device__ __forceinline__ void unpack2(u64 v, float& lo, float& hi) {
    asm("mov.b64 {%0, %1}, %2;" : "=f"(lo), "=f"(hi) : "l"(v));
}
__device__ __forceinline__ u64 relu2(u64 v) {
    float lo, hi; unpack2(v, lo, hi);
    return pack2(fmaxf(lo, 0.0f), fmaxf(hi, 0.0f));
}

// ---- bf16 split helpers ----
__device__ __forceinline__ float bf16r(float x) {
    return __bfloat162float(__float2bfloat16(x));
}
__device__ __forceinline__ u32 bf16pk(float lo, float hi) {
    __nv_bfloat162 t = __floats2bfloat162_rn(lo, hi);
    return reinterpret_cast<u32&>(t);
}
__device__ __forceinline__ u32 splitpk(float v) {
    const float h = bf16r(v);
    return bf16pk(h, v - h);
}

// mma.sync m16n8k16 bf16 (row.col), fp32 accumulate in-place
__device__ __forceinline__ void mma_bf16(float* d, const u32* a, const u32* b) {
    asm volatile(
        "mma.sync.aligned.m16n8k16.row.col.f32.bf16.bf16.f32 "
        "{%0,%1,%2,%3},{%4,%5,%6,%7},{%8,%9},{%0,%1,%2,%3};"
        : "+f"(d[0]), "+f"(d[1]), "+f"(d[2]), "+f"(d[3])
        : "r"(a[0]), "r"(a[1]), "r"(a[2]), "r"(a[3]), "r"(b[0]), "r"(b[1]));
}

// Intermediates
__device__ u32   g_h1b[(size_t)BATCH * 3610];        // conv1 out: split-bf16 u32
__device__ float g_h2[(size_t)BATCH * 20 * 100];     // conv2 out, planar fp32

// Pre-packed (w,w) fp32x2 weights (conv1, conv3, fc)
__device__ u64 g_w1p[1000];
__device__ u64 g_w3p[10000];
__device__ u64 g_wfp[7200];

// conv2 B fragments, linearized K: [kt(63)][nt(3)][var(2)][reg(2)][lane(32)]
__device__ u32 g_w2frag[63 * 3 * 2 * 2 * 32];

__global__ void pack_weights_kernel(
    const float* __restrict__ w1, const float* __restrict__ w3,
    const float* __restrict__ wf)
{
    const int i = blockIdx.x * 256 + threadIdx.x;
    if (i < 1000)  g_w1p[i] = pack2(w1[i], w1[i]);
    if (i < 10000) g_w3p[i] = pack2(w3[i], w3[i]);
    if (i < 7200)  g_wfp[i] = pack2(wf[i], wf[i]);
}

__global__ void pack_w2frag_kernel(const float* __restrict__ w2)
{
    int i = blockIdx.x * 256 + threadIdx.x;
    if (i >= 63 * 3 * 2 * 2 * 32) return;
    int lane = i & 31;  int rest = i >> 5;
    int reg = rest & 1; rest >>= 1;
    int var = rest & 1; rest >>= 1;
    int nt  = rest % 3;
    int kt  = rest / 3;

    int t4 = lane & 3, ocol = lane >> 2;
    int oc = nt * 8 + ocol;
    int k0 = kt * 16 + 2 * t4 + reg * 8;   // linear k = c*100 + ky*10 + kx
    float v0 = 0.0f, v1 = 0.0f;
    if (oc < 20) {
        if (k0 < 1000)     v0 = w2[oc * 1000 + k0];
        if (k0 + 1 < 1000) v1 = w2[oc * 1000 + k0 + 1];
    }
    float h0 = bf16r(v0), h1 = bf16r(v1);
    float o0 = (var == 0) ? h0 : (v0 - h0);
    float o1 = (var == 0) ? h1 : (v1 - h1);
    g_w2frag[i] = bf16pk(o0, o1);
}

// ---------------------------------------------------------------------------
// conv1 (unchanged champion): [1,28,28] -> relu -> [10,19,19], k10.
// One block per image PAIR, 96 threads. Stores split-bf16 u32 per image.
// ---------------------------------------------------------------------------
__global__ __launch_bounds__(96, 8) void conv1_kernel(
    const float* __restrict__ x, const float* __restrict__ b1)
{
    __shared__ u64 s_in2[28 * 29];
    const int bid = blockIdx.x;
    const int tid = threadIdx.x;

    const float* x0 = x + (size_t)(2 * bid) * 784;
    const float* x1 = x0 + 784;
    for (int i = tid; i < 784; i += 96) {
        const int r = i / 28, c = i % 28;
        s_in2[r * 29 + c] = pack2(x0[i], x1[i]);
    }
    __syncthreads();

    if (tid < 95) {
        const int ocg = tid / 19, oy = tid % 19;
        const int oc0 = 2 * ocg;
        const float bv0 = __ldg(&b1[oc0]), bv1 = __ldg(&b1[oc0 + 1]);
        const u64 bi0 = pack2(bv0, bv0), bi1 = pack2(bv1, bv1);
        u32* opA = &g_h1b[(size_t)(2 * bid) * 3610 + oc0 * 361 + oy * 19];
        u32* opB = opA + 3610;

        {   // pass A: q = 0..9
            u64 a0[10], a1[10];
            #pragma unroll
            for (int q = 0; q < 10; q++) { a0[q] = bi0; a1[q] = bi1; }
            for (int ky = 0; ky < 10; ky++) {
                u64 iv[19];
                const u64* rp = &s_in2[(oy + ky) * 29];
                #pragma unroll
                for (int j = 0; j < 19; j++) iv[j] = rp[j];
                const u64* w0p = &g_w1p[oc0 * 100 + ky * 10];
                const u64* w1p = w0p + 100;
                #pragma unroll
                for (int k2 = 0; k2 < 5; k2++) {
                    const ulonglong2 wa = __ldg((const ulonglong2*)(w0p + 2 * k2));
                    const ulonglong2 wb = __ldg((const ulonglong2*)(w1p + 2 * k2));
                    #pragma unroll
                    for (int q = 0; q < 10; q++) {
                        a0[q] = fma2(iv[q + 2 * k2],     wa.x, a0[q]);
                        a0[q] = fma2(iv[q + 2 * k2 + 1], wa.y, a0[q]);
                        a1[q] = fma2(iv[q + 2 * k2],     wb.x, a1[q]);
                        a1[q] = fma2(iv[q + 2 * k2 + 1], wb.y, a1[q]);
                    }
                }
            }
            #pragma unroll
            for (int q = 0; q < 10; q++) {
                float lo, hi;
                unpack2(a0[q], lo, hi);
                opA[q] = splitpk(fmaxf(lo, 0.0f));
                opB[q] = splitpk(fmaxf(hi, 0.0f));
                unpack2(a1[q], lo, hi);
                opA[361 + q] = splitpk(fmaxf(lo, 0.0f));
                opB[361 + q] = splitpk(fmaxf(hi, 0.0f));
            }
        }
        {   // pass B: q = 10..18
            u64 a0[9], a1[9];
            #pragma unroll
            for (int q = 0; q < 9; q++) { a0[q] = bi0; a1[q] = bi1; }
            for (int ky = 0; ky < 10; ky++) {
                u64 iv[18];
                const u64* rp = &s_in2[(oy + ky) * 29 + 10];
                #pragma unroll
                for (int j = 0; j < 18; j++) iv[j] = rp[j];
                const u64* w0p = &g_w1p[oc0 * 100 + ky * 10];
                const u64* w1p = w0p + 100;
                #pragma unroll
                for (int k2 = 0; k2 < 5; k2++) {
                    const ulonglong2 wa = __ldg((const ulonglong2*)(w0p + 2 * k2));
                    const ulonglong2 wb = __ldg((const ulonglong2*)(w1p + 2 * k2));
                    #pragma unroll
                    for (int q = 0; q < 9; q++) {
                        a0[q] = fma2(iv[q + 2 * k2],     wa.x, a0[q]);
                        a0[q] = fma2(iv[q + 2 * k2 + 1], wa.y, a0[q]);
                        a1[q] = fma2(iv[q + 2 * k2],     wb.x, a1[q]);
                        a1[q] = fma2(iv[q + 2 * k2 + 1], wb.y, a1[q]);
                    }
                }
            }
            #pragma unroll
            for (int q = 0; q < 9; q++) {
                float lo, hi;
                unpack2(a0[q], lo, hi);
                opA[10 + q] = splitpk(fmaxf(lo, 0.0f));
                opB[10 + q] = splitpk(fmaxf(hi, 0.0f));
                unpack2(a1[q], lo, hi);
                opA[371 + q] = splitpk(fmaxf(lo, 0.0f));
                opB[371 + q] = splitpk(fmaxf(hi, 0.0f));
            }
        }
    }
}

// ---------------------------------------------------------------------------
// conv2 tensor-core implicit GEMM, ONE image per block (grid 4096), 128 thr.
// smem: 4 bf16 planes (hi0, hi1-shifted, lo0, lo1-shifted), pitch 20 per row
// -> every A fragment pair is a single aligned LDS.32; zero PRMT in hot loop.
// koff lookup table kills per-epoch div/mod. B double-buffered in registers.
// ---------------------------------------------------------------------------
__global__ __launch_bounds__(128) void conv2_mma_kernel(const float* __restrict__ b2)
{
    __shared__ u32 s_pl[4 * 1900];   // planes: 0=hi0 1=hi1 2=lo0 3=lo1, u16[3800] each
    __shared__ u32 s_koff[63 * 8];   // [kt][t4][p] -> u32-index offset
    const int img = blockIdx.x;
    const int tid = threadIdx.x;
    const int wid = tid >> 5, lane = tid & 31;
    const int t4 = lane & 3, gr = lane >> 2;

    // --- loader: split packed u32 h1 into padded hi/lo planes + shifted copies
    {
        u16* hi0 = (u16*)&s_pl[0];
        u16* hi1 = (u16*)&s_pl[1900];
        u16* lo0 = (u16*)&s_pl[3800];
        u16* lo1 = (u16*)&s_pl[5700];
        const u32* h1p = &g_h1b[(size_t)img * 3610];
        for (int rr = tid; rr < 190; rr += 128) {       // rr = c*19 + iy
            const u32* src = h1p + rr * 19;
            const int dst = rr * 20;
            #pragma unroll
            for (int ix = 0; ix < 19; ix++) {
                const u32 v = src[ix];
                const u16 hi = (u16)(v & 0xffffu);
                const u16 lo = (u16)(v >> 16);
                hi0[dst + ix] = hi;
                lo0[dst + ix] = lo;
                if (ix > 0) {
                    hi1[dst + ix - 1] = hi;
                    lo1[dst + ix - 1] = lo;
                }
            }
        }
    }
    // --- koff table
    for (int i = tid; i < 504; i += 128) {
        const int kt = i >> 3, t4i = (i >> 1) & 3, p = i & 1;
        const int k0 = kt * 16 + 2 * t4i + 8 * p;
        s_koff[i] = (k0 < 1000)
            ? (u32)((k0 / 100) * 190 + ((k0 % 100) / 10) * 10 + ((k0 % 10) >> 1))
            : 0u;
    }

    float acc[2][3][4];
    #pragma unroll
    for (int mi = 0; mi < 2; mi++)
        #pragma unroll
        for (int nt = 0; nt < 3; nt++)
            #pragma unroll
            for (int r = 0; r < 4; r++) acc[mi][nt][r] = 0.0f;

    // A base u32-indices (plane-parity folded in): abase + koff indexes hi;
    // +3800 gives the matching lo plane.
    u32 abase[2][2];
    #pragma unroll
    for (int mi = 0; mi < 2; mi++) {
        const int m = wid + 4 * mi;
        #pragma unroll
        for (int h = 0; h < 2; h++) {
            const int r = m * 16 + gr + 8 * h;
            const bool v = (m < 7) && (r < 100);
            const int oy = r / 10, ox = r % 10;
            abase[mi][h] = v ? (u32)((ox & 1) * 1900 + oy * 10 + (ox >> 1)) : 0u;
        }
    }
    __syncthreads();

    // B double buffer
    u32 bc[12];
    {
        const u32* bp = &g_w2frag[lane];
        #pragma unroll
        for (int j = 0; j < 12; j++) bc[j] = __ldg(bp + j * 32);
    }

    #pragma unroll 1
    for (int kt = 0; kt < 63; kt++) {
        u32 bn[12];
        const int ktn = (kt < 62) ? (kt + 1) : 62;
        {
            const u32* bp = &g_w2frag[ktn * 384 + lane];
            #pragma unroll
            for (int j = 0; j < 12; j++) bn[j] = __ldg(bp + j * 32);
        }
        const u32 ko0 = s_koff[kt * 8 + t4 * 2];
        const u32 ko1 = s_koff[kt * 8 + t4 * 2 + 1];

        #pragma unroll
        for (int mi = 0; mi < 2; mi++) {
            if (wid + 4 * mi < 7) {
                u32 ahi[4], alo[4];
                #pragma unroll
                for (int h = 0; h < 2; h++) {
                    const u32 i0 = abase[mi][h] + ko0;
                    const u32 i1 = abase[mi][h] + ko1;
                    ahi[h]     = s_pl[i0];  alo[h]     = s_pl[i0 + 3800];
                    ahi[h + 2] = s_pl[i1];  alo[h + 2] = s_pl[i1 + 3800];
                }
                #pragma unroll
                for (int nt = 0; nt < 3; nt++) {
                    mma_bf16(acc[mi][nt], ahi, &bc[nt * 4]);      // ahi*bh
                    mma_bf16(acc[mi][nt], alo, &bc[nt * 4]);      // alo*bh
                    mma_bf16(acc[mi][nt], ahi, &bc[nt * 4 + 2]);  // ahi*bl
                }
            }
        }
        #pragma unroll
        for (int j = 0; j < 12; j++) bc[j] = bn[j];
    }

    // store: bias + relu, planar [img][oc][pos]
    #pragma unroll
    for (int mi = 0; mi < 2; mi++) {
        const int m = wid + 4 * mi;
        if (m >= 7) continue;
        #pragma unroll
        for (int h = 0; h < 2; h++) {
            const int r = m * 16 + gr + 8 * h;
            if (r >= 100) continue;
            float* op = &g_h2[(size_t)img * 2000 + r];
            #pragma unroll
            for (int nt = 0; nt < 3; nt++) {
                const int oc0 = nt * 8 + 2 * t4;
                if (oc0 < 20) {
                    const float v0 = acc[mi][nt][2 * h] + __ldg(&b2[oc0]);
                    op[oc0 * 100] = fmaxf(v0, 0.0f);
                }
                if (oc0 + 1 < 20) {
                    const float v1 = acc[mi][nt][2 * h + 1] + __ldg(&b2[oc0 + 1]);
                    op[(oc0 + 1) * 100] = fmaxf(v1, 0.0f);
                }
            }
        }
    }
}

// ---------------------------------------------------------------------------
// conv3 + FC (unchanged champion): one block per 2 image pairs, 128 threads.
// ---------------------------------------------------------------------------
__global__ __launch_bounds__(128) void conv3_fc_kernel(
    const float* __restrict__ b3, const float* __restrict__ bf,
    float* __restrict__ out)
{
    __shared__ u64 s_in2[2][2200];
    __shared__ u64 s_h2[2][720];
    __shared__ float s_rlo[4][10], s_rhi[4][10];

    const int bid = blockIdx.x;
    const int tid = threadIdx.x;
    const int p0 = 2 * bid;

    for (int i = tid; i < 4000; i += 128) {
        const int pq = i / 2000, rem = i % 2000;
        const int c = rem / 100, j = rem % 100;
        const int pr = p0 + pq;
        const float lo = g_h2[((size_t)(2 * pr)) * 2000 + c * 100 + j];
        const float hi = g_h2[((size_t)(2 * pr + 1)) * 2000 + c * 100 + j];
        s_in2[pq][c * 110 + (j / 10) * 11 + (j % 10)] = pack2(lo, hi);
    }

    const bool act = tid < 120;
    const int pp  = tid / 60;
    const int r   = tid % 60;
    const int ocg = r / 6, oy = r % 6;
    const int oc0 = 2 * ocg;

    u64 a0[6], a1[6];
    if (act) {
        const float bv0 = __ldg(&b3[oc0]), bv1 = __ldg(&b3[oc0 + 1]);
        const u64 bi0 = pack2(bv0, bv0), bi1 = pack2(bv1, bv1);
        #pragma unroll
        for (int q = 0; q < 6; q++) { a0[q] = bi0; a1[q] = bi1; }
    }
    __syncthreads();

    if (act) {
        for (int c = 0; c < 20; c++) {
            const u64* base = &s_in2[pp][c * 110];
            #pragma unroll
            for (int ky = 0; ky < 5; ky++) {
                u64 iv[10];
                const u64* rp = &base[(oy + ky) * 11];
                #pragma unroll
                for (int j = 0; j < 10; j++) iv[j] = rp[j];
                const u64* w0p = &g_w3p[oc0 * 500 + c * 25 + ky * 5];
                const u64* w1p = w0p + 500;
                #pragma unroll
                for (int kx = 0; kx < 5; kx++) {
                    const u64 w0  = __ldg(w0p + kx);
                    const u64 w1v = __ldg(w1p + kx);
                    #pragma unroll
                    for (int q = 0; q < 6; q++) {
                        a0[q] = fma2(iv[q + kx], w0,  a0[q]);
                        a1[q] = fma2(iv[q + kx], w1v, a1[q]);
                    }
                }
            }
        }
    }

    __syncthreads();
    if (act) {
        #pragma unroll
        for (int q = 0; q < 6; q++) {
            s_h2[pp][oc0 * 36 + oy * 6 + q]       = relu2(a0[q]);
            s_h2[pp][(oc0 + 1) * 36 + oy * 6 + q] = relu2(a1[q]);
        }
    }
    __syncthreads();

    {
        const int fpp = tid >> 6;
        const int j0  = tid & 63;
        u64 acc[10];
        #pragma unroll
        for (int o = 0; o < 10; o++) acc[o] = 0ULL;
        for (int j = j0; j < 720; j += 64) {
            const u64 v2 = s_h2[fpp][j];
            #pragma unroll
            for (int o = 0; o < 10; o++)
                acc[o] = fma2(v2, __ldg(&g_wfp[o * 720 + j]), acc[o]);
        }
        const int wd = tid >> 5;
        #pragma unroll
        for (int o = 0; o < 10; o++) {
            float lo, hi; unpack2(acc[o], lo, hi);
            #pragma unroll
            for (int s = 16; s > 0; s >>= 1) {
                lo += __shfl_down_sync(0xffffffffu, lo, s);
                hi += __shfl_down_sync(0xffffffffu, hi, s);
            }
            if ((tid & 31) == 0) { s_rlo[wd][o] = lo; s_rhi[wd][o] = hi; }
        }
    }
    __syncthreads();
    if (tid < 40) {
        const int o  = tid % 10;
        const int im = tid / 10;
        const int fpp  = im >> 1;
        const int half = im & 1;
        const int w0 = 2 * fpp;
        float v;
        if (half == 0) v = s_rlo[w0][o] + s_rlo[w0 + 1][o];
        else           v = s_rhi[w0][o] + s_rhi[w0 + 1][o];
        out[(size_t)(4 * bid + im) * 10 + o] = v + __ldg(&bf[o]);
    }
}

// ---------------------------------------------------------------------------
extern "C" void kernel_launch(void* const* d_in, const int* in_sizes, int n_in,
                              void* d_out, int out_size)
{
    (void)in_sizes; (void)n_in; (void)out_size;
    const float* x  = (const float*)d_in[0];
    const float* w1 = (const float*)d_in[1];
    const float* b1 = (const float*)d_in[2];
    const float* w2 = (const float*)d_in[3];
    const float* b2 = (const float*)d_in[4];
    const float* w3 = (const float*)d_in[5];
    const float* b3 = (const float*)d_in[6];
    const float* wf = (const float*)d_in[7];
    const float* bf = (const float*)d_in[8];
    float* out = (float*)d_out;

    pack_weights_kernel<<<40, 256>>>(w1, w3, wf);
    pack_w2frag_kernel<<<95, 256>>>(w2);
    conv1_kernel<<<NPAIR, 96>>>(x, b1);
    conv2_mma_kernel<<<BATCH, 128>>>(b2);
    conv3_fc_kernel<<<NPAIR / 2, 128>>>(b3, bf, out);
}